// round 4
// baseline (speedup 1.0000x reference)
#include <cuda_runtime.h>

// TranslateCube: out(y,x) = bilinear sample of in at (y - ty, x - tx), zero fill.
// [B*T, 256, 256] fp32; (tx, ty) constant per image.
//
// R3 lesson: L1tex wavefronts were the wall (91%). This version loads each
// input row segment as two ALIGNED float4s (cbase = x0 & ~3 is 16B-aligned,
// warp-uniform lane offset m = x0 & 3), then selects the 5 needed values.
// OOB handled by clamping load addresses + zeroing masked values — no
// divergent fallback, no fault risk.

#define HH 256
#define WW 256
#define PX 4                 // pixels per thread (x)
#define CGRP (WW / PX)       // 64 column groups
#define RY 4                 // rows covered by blockDim.y
#define ROWS_PER_BLOCK 8

// Pick p[0..4] = v[m .. m+4] from the 8 floats {L, H}; m is warp-uniform.
__device__ __forceinline__ void sel5(float& p0, float& p1, float& p2,
                                     float& p3, float& p4,
                                     const float4 L, const float4 H, int m)
{
    switch (m) {
    case 0: p0 = L.x; p1 = L.y; p2 = L.z; p3 = L.w; p4 = H.x; break;
    case 1: p0 = L.y; p1 = L.z; p2 = L.w; p3 = H.x; p4 = H.y; break;
    case 2: p0 = L.z; p1 = L.w; p2 = H.x; p3 = H.y; p4 = H.z; break;
    default:p0 = L.w; p1 = H.x; p2 = H.y; p3 = H.z; p4 = H.w; break;
    }
}

__global__ __launch_bounds__(256) void translate_kernel(
    const float* __restrict__ img,
    const float* __restrict__ dx,
    const float* __restrict__ dy,
    float* __restrict__ out)
{
    const int imgIdx = blockIdx.y;
    const int yBase  = blockIdx.x * ROWS_PER_BLOCK + threadIdx.y;
    const float tx = __ldg(dx + imgIdx);
    const float ty = __ldg(dy + imgIdx);

    const int c = threadIdx.x;      // column group 0..63
    const int x = c * PX;           // first output column

    const float sx0 = (float)x - tx;
    const int   x0  = (int)floorf(sx0);
    const int   m   = x0 & 3;            // warp-uniform lane offset
    const int   cbase = x0 - m;          // 16B-aligned column base

    // Clamped (always-in-bounds) float4 column indices for the two loads.
    const int q0 = min(max(cbase,     0), WW - 4) >> 2;
    const int q1 = min(max(cbase + 4, 0), WW - 4) >> 2;

    // Per-pixel fractional weights (reference fp32 expression) + validity.
    float wx[PX];
    bool  vx[PX + 1];
    #pragma unroll
    for (int j = 0; j < PX; ++j)
        wx[j] = ((float)(x + j) - tx) - (float)(x0 + j);
    #pragma unroll
    for (int j = 0; j <= PX; ++j)
        vx[j] = (unsigned)(x0 + j) < (unsigned)WW;

    const float* base  = img + (size_t)imgIdx * (HH * WW);
    float4*      obase = (float4*)(out + (size_t)imgIdx * (HH * WW));

    #pragma unroll
    for (int k = 0; k < ROWS_PER_BLOCK / RY; ++k) {
        const int y = yBase + k * RY;
        const float sy  = (float)y - ty;
        const float y0f = floorf(sy);
        const float wy  = sy - y0f;
        const int   y0  = (int)y0f;
        const bool  vy0 = (unsigned)y0       < (unsigned)HH;
        const bool  vy1 = (unsigned)(y0 + 1) < (unsigned)HH;
        const int   y0c = min(max(y0,     0), HH - 1);
        const int   y1c = min(max(y0 + 1, 0), HH - 1);

        const float4* r0 = (const float4*)(base + (size_t)y0c * WW);
        const float4* r1 = (const float4*)(base + (size_t)y1c * WW);

        const float4 A0 = __ldg(r0 + q0);
        const float4 A1 = __ldg(r0 + q1);
        const float4 B0 = __ldg(r1 + q0);
        const float4 B1 = __ldg(r1 + q1);

        float a0, a1, a2, a3, a4, b0, b1, b2, b3, b4;
        sel5(a0, a1, a2, a3, a4, A0, A1, m);
        sel5(b0, b1, b2, b3, b4, B0, B1, m);

        float a[PX + 1] = {a0, a1, a2, a3, a4};
        float b[PX + 1] = {b0, b1, b2, b3, b4};
        #pragma unroll
        for (int j = 0; j <= PX; ++j) {
            a[j] = (vy0 && vx[j]) ? a[j] : 0.0f;
            b[j] = (vy1 && vx[j]) ? b[j] : 0.0f;
        }

        float o[PX];
        #pragma unroll
        for (int j = 0; j < PX; ++j) {
            const float top = fmaf(wx[j], a[j + 1] - a[j], a[j]);
            const float bot = fmaf(wx[j], b[j + 1] - b[j], b[j]);
            o[j] = fmaf(wy, bot - top, top);
        }
        __stcs(&obase[y * CGRP + c], make_float4(o[0], o[1], o[2], o[3]));
    }
}

extern "C" void kernel_launch(void* const* d_in, const int* in_sizes, int n_in,
                              void* d_out, int out_size) {
    const float* images = (const float*)d_in[0];
    const float* dx     = (const float*)d_in[1];
    const float* dy     = (const float*)d_in[2];
    // d_in[3] is winsize (unused by the math)
    float* out = (float*)d_out;

    const int n_images = in_sizes[1];  // B*T (dx element count)

    dim3 block(CGRP, RY);              // 64 x 4 = 256 threads
    dim3 grid(HH / ROWS_PER_BLOCK, n_images);
    translate_kernel<<<grid, block>>>(images, dx, dy, out);
}

// round 5
// speedup vs baseline: 1.0468x; 1.0468x over previous
#include <cuda_runtime.h>

// TranslateCube: out(y,x) = bilinear(in, y - ty, x - tx), zero fill.
// [B*T, 256, 256] fp32; (tx, ty) constant per image.
//
// R4 lesson: SEL chains (misalignment select + validity masks) made the
// kernel ALU/issue bound. Fixes:
//  - m = x0 & 3 is uniform per image -> template-specialize on M, selection
//    becomes register renaming (0 instr).
//  - row validity folded into scalar weights wtop/wbot (clamped row ptrs).
//  - column masks only on the <=2 edge column-groups (uniform branch).

#define HH 256
#define WW 256
#define PX 4
#define CGRP (WW / PX)       // 64
#define RY 4
#define RPB 8                // rows per block

template <int M>
__device__ __forceinline__ void sel5c(float a[5], const float4 L, const float4 H)
{
    const float v[8] = {L.x, L.y, L.z, L.w, H.x, H.y, H.z, H.w};
#pragma unroll
    for (int j = 0; j < 5; ++j) a[j] = v[M + j];
}

template <int M>
__device__ __forceinline__ void run_image(
    const float* __restrict__ base, float4* __restrict__ obase,
    int yBase, int c, int x0, int cbase, const float* wx, float ty)
{
    const bool interior = (x0 >= 0) && (x0 + PX <= WW - 1);

    if (interior) {
        const int q0 = cbase >> 2;           // cbase in [0,248] when interior
#pragma unroll
        for (int k = 0; k < RPB / RY; ++k) {
            const int y = yBase + k * RY;
            const float sy  = (float)y - ty;
            const float y0f = floorf(sy);
            const float wy  = sy - y0f;
            const int   y0  = (int)y0f;
            const float wtop = ((unsigned)y0       < (unsigned)HH) ? (1.0f - wy) : 0.0f;
            const float wbot = ((unsigned)(y0 + 1) < (unsigned)HH) ? wy          : 0.0f;
            const int y0c = min(max(y0,     0), HH - 1);
            const int y1c = min(max(y0 + 1, 0), HH - 1);

            const float4* r0 = (const float4*)(base + (size_t)y0c * WW);
            const float4* r1 = (const float4*)(base + (size_t)y1c * WW);
            const float4 A0 = __ldg(r0 + q0), A1 = __ldg(r0 + q0 + 1);
            const float4 B0 = __ldg(r1 + q0), B1 = __ldg(r1 + q0 + 1);

            float a[5], b[5];
            sel5c<M>(a, A0, A1);
            sel5c<M>(b, B0, B1);

            float o[PX];
#pragma unroll
            for (int j = 0; j < PX; ++j) {
                const float top = fmaf(wx[j], a[j + 1] - a[j], a[j]);
                const float bot = fmaf(wx[j], b[j + 1] - b[j], b[j]);
                o[j] = fmaf(wtop, top, wbot * bot);
            }
            __stcs(&obase[y * CGRP + c], make_float4(o[0], o[1], o[2], o[3]));
        }
    } else {
        const int q0 = min(max(cbase,     0), WW - 4) >> 2;
        const int q1 = min(max(cbase + 4, 0), WW - 4) >> 2;
        bool vx[PX + 1];
#pragma unroll
        for (int j = 0; j <= PX; ++j)
            vx[j] = (unsigned)(x0 + j) < (unsigned)WW;

#pragma unroll
        for (int k = 0; k < RPB / RY; ++k) {
            const int y = yBase + k * RY;
            const float sy  = (float)y - ty;
            const float y0f = floorf(sy);
            const float wy  = sy - y0f;
            const int   y0  = (int)y0f;
            const float wtop = ((unsigned)y0       < (unsigned)HH) ? (1.0f - wy) : 0.0f;
            const float wbot = ((unsigned)(y0 + 1) < (unsigned)HH) ? wy          : 0.0f;
            const int y0c = min(max(y0,     0), HH - 1);
            const int y1c = min(max(y0 + 1, 0), HH - 1);

            const float4* r0 = (const float4*)(base + (size_t)y0c * WW);
            const float4* r1 = (const float4*)(base + (size_t)y1c * WW);
            const float4 A0 = __ldg(r0 + q0), A1 = __ldg(r0 + q1);
            const float4 B0 = __ldg(r1 + q0), B1 = __ldg(r1 + q1);

            float a[5], b[5];
            sel5c<M>(a, A0, A1);
            sel5c<M>(b, B0, B1);
#pragma unroll
            for (int j = 0; j <= PX; ++j) {
                a[j] = vx[j] ? a[j] : 0.0f;
                b[j] = vx[j] ? b[j] : 0.0f;
            }

            float o[PX];
#pragma unroll
            for (int j = 0; j < PX; ++j) {
                const float top = fmaf(wx[j], a[j + 1] - a[j], a[j]);
                const float bot = fmaf(wx[j], b[j + 1] - b[j], b[j]);
                o[j] = fmaf(wtop, top, wbot * bot);
            }
            __stcs(&obase[y * CGRP + c], make_float4(o[0], o[1], o[2], o[3]));
        }
    }
}

__global__ __launch_bounds__(256) void translate_kernel(
    const float* __restrict__ img,
    const float* __restrict__ dx,
    const float* __restrict__ dy,
    float* __restrict__ out)
{
    const int imgIdx = blockIdx.y;
    const int yBase  = blockIdx.x * RPB + threadIdx.y;
    const float tx = __ldg(dx + imgIdx);
    const float ty = __ldg(dy + imgIdx);

    const int c = threadIdx.x;      // column group 0..63
    const int x = c * PX;

    const float sx0 = (float)x - tx;
    const int   x0  = (int)floorf(sx0);
    const int   m   = x0 & 3;       // uniform per image
    const int   cbase = x0 - m;

    float wx[PX];
#pragma unroll
    for (int j = 0; j < PX; ++j)
        wx[j] = ((float)(x + j) - tx) - (float)(x0 + j);

    const float* base  = img + (size_t)imgIdx * (HH * WW);
    float4*      obase = (float4*)(out + (size_t)imgIdx * (HH * WW));

    switch (m) {
    case 0:  run_image<0>(base, obase, yBase, c, x0, cbase, wx, ty); break;
    case 1:  run_image<1>(base, obase, yBase, c, x0, cbase, wx, ty); break;
    case 2:  run_image<2>(base, obase, yBase, c, x0, cbase, wx, ty); break;
    default: run_image<3>(base, obase, yBase, c, x0, cbase, wx, ty); break;
    }
}

extern "C" void kernel_launch(void* const* d_in, const int* in_sizes, int n_in,
                              void* d_out, int out_size) {
    const float* images = (const float*)d_in[0];
    const float* dx     = (const float*)d_in[1];
    const float* dy     = (const float*)d_in[2];
    // d_in[3] is winsize (unused by the math)
    float* out = (float*)d_out;

    const int n_images = in_sizes[1];  // B*T

    dim3 block(CGRP, RY);              // 64 x 4 = 256 threads
    dim3 grid(HH / RPB, n_images);
    translate_kernel<<<grid, block>>>(images, dx, dy, out);
}

// round 6
// speedup vs baseline: 1.0696x; 1.0217x over previous
#include <cuda_runtime.h>

// TranslateCube: out(y,x) = bilinear(in, y - ty, x - tx), zero fill.
// [B*T, 256, 256] fp32; (tx, ty) constant per image.
//
// 8 px/thread, 1 row/thread (32 threads per row). Column validity and
// horizontal weights pre-folded into u0/u1 once per thread -> the per-row
// body is pure loads + FMA + store (no SEL, no branches). Row validity
// folded into scalar weights wtop/wbot with clamped row addresses.
// m = x0 & 3 is uniform per image -> template renaming for the window select.

#define HH 256
#define WW 256
#define PX 8
#define TPR (WW / PX)        // 32 threads per row
#define RPB 8                // rows per block

template <int M>
__device__ __forceinline__ void run(
    const float* __restrict__ base, float4* __restrict__ obase,
    int y, int c, int qa, int qb, int qc,
    const float* __restrict__ u0, const float* __restrict__ u1, float ty)
{
    const float sy  = (float)y - ty;
    const float y0f = floorf(sy);
    const float wy  = sy - y0f;
    const int   y0  = (int)y0f;
    const float wtop = ((unsigned)y0       < (unsigned)HH) ? (1.0f - wy) : 0.0f;
    const float wbot = ((unsigned)(y0 + 1) < (unsigned)HH) ? wy          : 0.0f;
    const int y0c = min(max(y0,     0), HH - 1);
    const int y1c = min(max(y0 + 1, 0), HH - 1);

    const float4* r0 = (const float4*)(base + (size_t)y0c * WW);
    const float4* r1 = (const float4*)(base + (size_t)y1c * WW);

    const float4 A0 = __ldg(r0 + qa), A1 = __ldg(r0 + qb), A2 = __ldg(r0 + qc);
    const float4 B0 = __ldg(r1 + qa), B1 = __ldg(r1 + qb), B2 = __ldg(r1 + qc);

    const float va[12] = {A0.x, A0.y, A0.z, A0.w, A1.x, A1.y, A1.z, A1.w,
                          A2.x, A2.y, A2.z, A2.w};
    const float vb[12] = {B0.x, B0.y, B0.z, B0.w, B1.x, B1.y, B1.z, B1.w,
                          B2.x, B2.y, B2.z, B2.w};

    float o[PX];
#pragma unroll
    for (int j = 0; j < PX; ++j) {
        const float a0 = va[M + j], a1 = va[M + j + 1];
        const float b0 = vb[M + j], b1 = vb[M + j + 1];
        const float t = fmaf(u1[j], a1, u0[j] * a0);
        const float s = fmaf(u1[j], b1, u0[j] * b0);
        o[j] = fmaf(wbot, s, wtop * t);
    }
    float4* dst = &obase[y * (WW / 4) + c * 2];
    __stcs(dst,     make_float4(o[0], o[1], o[2], o[3]));
    __stcs(dst + 1, make_float4(o[4], o[5], o[6], o[7]));
}

__global__ __launch_bounds__(256) void translate_kernel(
    const float* __restrict__ img,
    const float* __restrict__ dx,
    const float* __restrict__ dy,
    float* __restrict__ out)
{
    const int imgIdx = blockIdx.y;
    const float tx = __ldg(dx + imgIdx);
    const float ty = __ldg(dy + imgIdx);

    const int c = threadIdx.x;             // 0..31
    const int x = c * PX;
    const int y = blockIdx.x * RPB + threadIdx.y;

    const int   x0 = (int)floorf((float)x - tx);
    const int   m  = x0 & 3;               // uniform per image
    const int   cbase = x0 - m;

    // Clamped, always-in-bounds float4 chunk indices (OOB lanes get zero weight).
    const int qa = min(max(cbase,     0), WW - 4) >> 2;
    const int qb = min(max(cbase + 4, 0), WW - 4) >> 2;
    const int qc = min(max(cbase + 8, 0), WW - 4) >> 2;

    // Precompute horizontal weights with column validity folded in.
    float u0[PX], u1[PX];
#pragma unroll
    for (int j = 0; j < PX; ++j) {
        const float wx = ((float)(x + j) - tx) - (float)(x0 + j);
        const bool v0 = (unsigned)(x0 + j)     < (unsigned)WW;
        const bool v1 = (unsigned)(x0 + j + 1) < (unsigned)WW;
        u0[j] = v0 ? (1.0f - wx) : 0.0f;
        u1[j] = v1 ? wx          : 0.0f;
    }

    const float* base  = img + (size_t)imgIdx * (HH * WW);
    float4*      obase = (float4*)(out + (size_t)imgIdx * (HH * WW));

    switch (m) {
    case 0:  run<0>(base, obase, y, c, qa, qb, qc, u0, u1, ty); break;
    case 1:  run<1>(base, obase, y, c, qa, qb, qc, u0, u1, ty); break;
    case 2:  run<2>(base, obase, y, c, qa, qb, qc, u0, u1, ty); break;
    default: run<3>(base, obase, y, c, qa, qb, qc, u0, u1, ty); break;
    }
}

extern "C" void kernel_launch(void* const* d_in, const int* in_sizes, int n_in,
                              void* d_out, int out_size) {
    const float* images = (const float*)d_in[0];
    const float* dx     = (const float*)d_in[1];
    const float* dy     = (const float*)d_in[2];
    // d_in[3] is winsize (unused by the math)
    float* out = (float*)d_out;

    const int n_images = in_sizes[1];  // B*T

    dim3 block(TPR, RPB);              // 32 x 8 = 256 threads
    dim3 grid(HH / RPB, n_images);
    translate_kernel<<<grid, block>>>(images, dx, dy, out);
}

// round 7
// speedup vs baseline: 1.0926x; 1.0215x over previous
#include <cuda_runtime.h>

// TranslateCube: out(y,x) = bilinear(in, y - ty, x - tx), zero fill.
// [B*T, 256, 256] fp32; (tx, ty) constant per image.
//
// 8 px/thread in x, 4 rows/thread in y (32 px/thread): the column prologue
// (weights u0/u1 with validity folded in, chunk indices, misalignment
// template M) is computed ONCE and reused across 4 independent rows.
// Rows carry no register dependencies -> all 24 LDG.128 can be in flight.

#define HH 256
#define WW 256
#define PX 8
#define TPR (WW / PX)        // 32 threads per row (one warp = one row)
#define WPB 8                // warps per block
#define RPT 4                // rows per thread
#define RPB (WPB * RPT)      // 32 rows per block

template <int M>
__device__ __forceinline__ void run4(
    const float* __restrict__ base, float4* __restrict__ obase,
    int yBase, int c, int qa, int qb, int qc,
    const float* __restrict__ u0, const float* __restrict__ u1, float ty)
{
#pragma unroll
    for (int r = 0; r < RPT; ++r) {
        const int y = yBase + r;
        const float sy  = (float)y - ty;
        const float y0f = floorf(sy);
        const float wy  = sy - y0f;
        const int   y0  = (int)y0f;
        const float wtop = ((unsigned)y0       < (unsigned)HH) ? (1.0f - wy) : 0.0f;
        const float wbot = ((unsigned)(y0 + 1) < (unsigned)HH) ? wy          : 0.0f;
        const int y0c = min(max(y0,     0), HH - 1);
        const int y1c = min(max(y0 + 1, 0), HH - 1);

        const float4* r0 = (const float4*)(base + (size_t)y0c * WW);
        const float4* r1 = (const float4*)(base + (size_t)y1c * WW);

        const float4 A0 = __ldg(r0 + qa), A1 = __ldg(r0 + qb), A2 = __ldg(r0 + qc);
        const float4 B0 = __ldg(r1 + qa), B1 = __ldg(r1 + qb), B2 = __ldg(r1 + qc);

        const float va[12] = {A0.x, A0.y, A0.z, A0.w, A1.x, A1.y, A1.z, A1.w,
                              A2.x, A2.y, A2.z, A2.w};
        const float vb[12] = {B0.x, B0.y, B0.z, B0.w, B1.x, B1.y, B1.z, B1.w,
                              B2.x, B2.y, B2.z, B2.w};

        float o[PX];
#pragma unroll
        for (int j = 0; j < PX; ++j) {
            const float t = fmaf(u1[j], va[M + j + 1], u0[j] * va[M + j]);
            const float s = fmaf(u1[j], vb[M + j + 1], u0[j] * vb[M + j]);
            o[j] = fmaf(wbot, s, wtop * t);
        }
        float4* dst = &obase[y * (WW / 4) + c * 2];
        __stcs(dst,     make_float4(o[0], o[1], o[2], o[3]));
        __stcs(dst + 1, make_float4(o[4], o[5], o[6], o[7]));
    }
}

__global__ __launch_bounds__(256, 4) void translate_kernel(
    const float* __restrict__ img,
    const float* __restrict__ dx,
    const float* __restrict__ dy,
    float* __restrict__ out)
{
    const int imgIdx = blockIdx.y;
    const float tx = __ldg(dx + imgIdx);
    const float ty = __ldg(dy + imgIdx);

    const int c = threadIdx.x;                       // 0..31
    const int x = c * PX;
    const int yBase = blockIdx.x * RPB + threadIdx.y * RPT;

    const int   x0 = (int)floorf((float)x - tx);
    const int   m  = x0 & 3;                         // uniform per image
    const int   cbase = x0 - m;

    // Clamped, always-in-bounds float4 chunk indices (OOB lanes get 0 weight).
    const int qa = min(max(cbase,     0), WW - 4) >> 2;
    const int qb = min(max(cbase + 4, 0), WW - 4) >> 2;
    const int qc = min(max(cbase + 8, 0), WW - 4) >> 2;

    // Horizontal weights with column validity folded in (once per 32 px).
    float u0[PX], u1[PX];
#pragma unroll
    for (int j = 0; j < PX; ++j) {
        const float wx = ((float)(x + j) - tx) - (float)(x0 + j);
        const bool v0 = (unsigned)(x0 + j)     < (unsigned)WW;
        const bool v1 = (unsigned)(x0 + j + 1) < (unsigned)WW;
        u0[j] = v0 ? (1.0f - wx) : 0.0f;
        u1[j] = v1 ? wx          : 0.0f;
    }

    const float* base  = img + (size_t)imgIdx * (HH * WW);
    float4*      obase = (float4*)(out + (size_t)imgIdx * (HH * WW));

    switch (m) {
    case 0:  run4<0>(base, obase, yBase, c, qa, qb, qc, u0, u1, ty); break;
    case 1:  run4<1>(base, obase, yBase, c, qa, qb, qc, u0, u1, ty); break;
    case 2:  run4<2>(base, obase, yBase, c, qa, qb, qc, u0, u1, ty); break;
    default: run4<3>(base, obase, yBase, c, qa, qb, qc, u0, u1, ty); break;
    }
}

extern "C" void kernel_launch(void* const* d_in, const int* in_sizes, int n_in,
                              void* d_out, int out_size) {
    const float* images = (const float*)d_in[0];
    const float* dx     = (const float*)d_in[1];
    const float* dy     = (const float*)d_in[2];
    // d_in[3] is winsize (unused by the math)
    float* out = (float*)d_out;

    const int n_images = in_sizes[1];  // B*T

    dim3 block(TPR, WPB);              // 32 x 8 = 256 threads
    dim3 grid(HH / RPB, n_images);     // 8 x 1024
    translate_kernel<<<grid, block>>>(images, dx, dy, out);
}

// round 8
// speedup vs baseline: 1.1150x; 1.0205x over previous
#include <cuda_runtime.h>

// TranslateCube: out(y,x) = bilinear(in, y - ty, x - tx), zero fill.
// [B*T, 256, 256] fp32; (tx, ty) constant per image.
//
// R7 lesson: RPT=4 cost 64 regs -> 41.7% occ -> latency-bound (issue 29%,
// DRAM 66%). This round: RPT=2 halves register pressure (~46 regs, 5-6
// blocks/SM) while keeping 12 independent LDG.128 in flight per thread.
// Column prologue (u0/u1 weights with validity folded in, chunk indices,
// misalignment template M) still amortized across both rows.

#define HH 256
#define WW 256
#define PX 8
#define TPR (WW / PX)        // 32 threads per row (one warp = one row)
#define WPB 8                // warps per block
#define RPT 2                // rows per thread
#define RPB (WPB * RPT)      // 16 rows per block

template <int M>
__device__ __forceinline__ void run_rows(
    const float* __restrict__ base, float4* __restrict__ obase,
    int yBase, int c, int qa, int qb, int qc,
    const float* __restrict__ u0, const float* __restrict__ u1, float ty)
{
#pragma unroll
    for (int r = 0; r < RPT; ++r) {
        const int y = yBase + r;
        const float sy  = (float)y - ty;
        const float y0f = floorf(sy);
        const float wy  = sy - y0f;
        const int   y0  = (int)y0f;
        const float wtop = ((unsigned)y0       < (unsigned)HH) ? (1.0f - wy) : 0.0f;
        const float wbot = ((unsigned)(y0 + 1) < (unsigned)HH) ? wy          : 0.0f;
        const int y0c = min(max(y0,     0), HH - 1);
        const int y1c = min(max(y0 + 1, 0), HH - 1);

        const float4* r0 = (const float4*)(base + (size_t)y0c * WW);
        const float4* r1 = (const float4*)(base + (size_t)y1c * WW);

        const float4 A0 = __ldg(r0 + qa), A1 = __ldg(r0 + qb), A2 = __ldg(r0 + qc);
        const float4 B0 = __ldg(r1 + qa), B1 = __ldg(r1 + qb), B2 = __ldg(r1 + qc);

        const float va[12] = {A0.x, A0.y, A0.z, A0.w, A1.x, A1.y, A1.z, A1.w,
                              A2.x, A2.y, A2.z, A2.w};
        const float vb[12] = {B0.x, B0.y, B0.z, B0.w, B1.x, B1.y, B1.z, B1.w,
                              B2.x, B2.y, B2.z, B2.w};

        float o[PX];
#pragma unroll
        for (int j = 0; j < PX; ++j) {
            const float t = fmaf(u1[j], va[M + j + 1], u0[j] * va[M + j]);
            const float s = fmaf(u1[j], vb[M + j + 1], u0[j] * vb[M + j]);
            o[j] = fmaf(wbot, s, wtop * t);
        }
        float4* dst = &obase[y * (WW / 4) + c * 2];
        __stcs(dst,     make_float4(o[0], o[1], o[2], o[3]));
        __stcs(dst + 1, make_float4(o[4], o[5], o[6], o[7]));
    }
}

__global__ __launch_bounds__(256) void translate_kernel(
    const float* __restrict__ img,
    const float* __restrict__ dx,
    const float* __restrict__ dy,
    float* __restrict__ out)
{
    const int imgIdx = blockIdx.y;
    const float tx = __ldg(dx + imgIdx);
    const float ty = __ldg(dy + imgIdx);

    const int c = threadIdx.x;                       // 0..31
    const int x = c * PX;
    const int yBase = blockIdx.x * RPB + threadIdx.y * RPT;

    const int   x0 = (int)floorf((float)x - tx);
    const int   m  = x0 & 3;                         // uniform per image
    const int   cbase = x0 - m;

    // Clamped, always-in-bounds float4 chunk indices (OOB lanes get 0 weight).
    const int qa = min(max(cbase,     0), WW - 4) >> 2;
    const int qb = min(max(cbase + 4, 0), WW - 4) >> 2;
    const int qc = min(max(cbase + 8, 0), WW - 4) >> 2;

    // Horizontal weights with column validity folded in (once per 16 px).
    float u0[PX], u1[PX];
#pragma unroll
    for (int j = 0; j < PX; ++j) {
        const float wx = ((float)(x + j) - tx) - (float)(x0 + j);
        const bool v0 = (unsigned)(x0 + j)     < (unsigned)WW;
        const bool v1 = (unsigned)(x0 + j + 1) < (unsigned)WW;
        u0[j] = v0 ? (1.0f - wx) : 0.0f;
        u1[j] = v1 ? wx          : 0.0f;
    }

    const float* base  = img + (size_t)imgIdx * (HH * WW);
    float4*      obase = (float4*)(out + (size_t)imgIdx * (HH * WW));

    switch (m) {
    case 0:  run_rows<0>(base, obase, yBase, c, qa, qb, qc, u0, u1, ty); break;
    case 1:  run_rows<1>(base, obase, yBase, c, qa, qb, qc, u0, u1, ty); break;
    case 2:  run_rows<2>(base, obase, yBase, c, qa, qb, qc, u0, u1, ty); break;
    default: run_rows<3>(base, obase, yBase, c, qa, qb, qc, u0, u1, ty); break;
    }
}

extern "C" void kernel_launch(void* const* d_in, const int* in_sizes, int n_in,
                              void* d_out, int out_size) {
    const float* images = (const float*)d_in[0];
    const float* dx     = (const float*)d_in[1];
    const float* dy     = (const float*)d_in[2];
    // d_in[3] is winsize (unused by the math)
    float* out = (float*)d_out;

    const int n_images = in_sizes[1];  // B*T

    dim3 block(TPR, WPB);              // 32 x 8 = 256 threads
    dim3 grid(HH / RPB, n_images);     // 16 x 1024
    translate_kernel<<<grid, block>>>(images, dx, dy, out);
}